// round 16
// baseline (speedup 1.0000x reference)
#include <cuda_runtime.h>
#include <cuda_bf16.h>

#define B_  4
#define S_  512
#define D_  512
#define H_  16
#define DH_ 32
#define E_  128

typedef unsigned long long ull;

// ---- f32x2 packed-math helpers (sm_103a FFMA2 path, PTX-only) -------------
__device__ __forceinline__ ull pack2(float x, float y) {
    ull r; asm("mov.b64 %0, {%1, %2};" : "=l"(r) : "f"(x), "f"(y)); return r;
}
__device__ __forceinline__ void ffma2(ull& d, ull a, ull b) {
    asm("fma.rn.f32x2 %0, %1, %2, %0;" : "+l"(d) : "l"(a), "l"(b));
}
__device__ __forceinline__ ull fmul2(ull a, ull b) {
    ull r; asm("mul.rn.f32x2 %0, %1, %2;" : "=l"(r) : "l"(a), "l"(b)); return r;
}
__device__ __forceinline__ float2 unpack2(ull v) {
    float2 f; asm("mov.b64 {%0, %1}, %2;" : "=f"(f.x), "=f"(f.y) : "l"(v)); return f;
}

// scale * log2(e): scores pre-multiplied so softmax uses exp2f directly.
#define SCALE_L2E (0.10206207261596576f * 1.4426950408889634f)
#define MASKED_SCORE (-1e30f)

// fp32 scratch (static device globals; no allocation anywhere)
__device__ float g_Q[B_*H_*S_*DH_];
__device__ float g_K[B_*H_*S_*DH_];
__device__ float g_V[B_*H_*S_*DH_];
__device__ float g_P0[2048 * 1536];     // split-K partial 0
__device__ float g_P1[2048 * 1536];     // split-K partial 1
__device__ float g_RADD[B_*H_*S_*S_];   // folded edge term * SCALE_L2E, mask folded in

// ---------------------------------------------------------------------------
// Kernel A: split-K qkv GEMM (unchanged from R14).
// ---------------------------------------------------------------------------
__global__ void __launch_bounds__(256) qkv_gemm_kernel(
    const float* __restrict__ X, const float* __restrict__ W)
{
    __shared__ __align__(16) float As[2][8 * 132];
    __shared__ __align__(16) float Bs[2][8 * 128];

    const int m0 = blockIdx.y * 128;
    const int n0 = blockIdx.x * 128;
    const int ks = blockIdx.z * 256;
    float* __restrict__ Pout = blockIdx.z ? g_P1 : g_P0;

    const int tid = threadIdx.x;
    const int tx = tid & 15;
    const int ty = tid >> 4;

    const int lm  = tid >> 1;
    const int lkq = (tid & 1) * 4;
    const int lkr = tid >> 5;
    const int lnq = (tid & 31) * 4;

    const float* Ag = X + (size_t)(m0 + lm) * 512 + ks + lkq;
    const float* Bg = W + (size_t)(ks + lkr) * 1536 + n0 + lnq;

    ull acc2[8][4];
#pragma unroll
    for (int i = 0; i < 8; i++)
#pragma unroll
        for (int j = 0; j < 4; j++) acc2[i][j] = 0ULL;

    {
        float4 av = *(const float4*)(Ag);
        float4 bv = *(const float4*)(Bg);
        As[0][(lkq + 0) * 132 + lm] = av.x;
        As[0][(lkq + 1) * 132 + lm] = av.y;
        As[0][(lkq + 2) * 132 + lm] = av.z;
        As[0][(lkq + 3) * 132 + lm] = av.w;
        *(float4*)(&Bs[0][lkr * 128 + lnq]) = bv;
    }
    __syncthreads();

    int buf = 0;
    for (int k0 = 0; k0 < 256; k0 += 8) {
        const bool has_next = (k0 + 8) < 256;
        float4 av, bv;
        if (has_next) {
            av = *(const float4*)(Ag + k0 + 8);
            bv = *(const float4*)(Bg + (size_t)(k0 + 8) * 1536);
        }

        const float* Asb = As[buf];
        const float* Bsb = Bs[buf];
#pragma unroll
        for (int kk = 0; kk < 8; kk++) {
            float a[8];
            *(float4*)(a)     = *(const float4*)(Asb + kk * 132 + ty * 8);
            *(float4*)(a + 4) = *(const float4*)(Asb + kk * 132 + ty * 8 + 4);
            ulonglong2 b01 = *(const ulonglong2*)(Bsb + kk * 128 + tx * 8);
            ulonglong2 b23 = *(const ulonglong2*)(Bsb + kk * 128 + tx * 8 + 4);
            ull bp0 = b01.x, bp1 = b01.y, bp2 = b23.x, bp3 = b23.y;
#pragma unroll
            for (int i = 0; i < 8; i++) {
                const ull ap = pack2(a[i], a[i]);
                ffma2(acc2[i][0], ap, bp0);
                ffma2(acc2[i][1], ap, bp1);
                ffma2(acc2[i][2], ap, bp2);
                ffma2(acc2[i][3], ap, bp3);
            }
        }

        if (has_next) {
            const int nb = buf ^ 1;
            As[nb][(lkq + 0) * 132 + lm] = av.x;
            As[nb][(lkq + 1) * 132 + lm] = av.y;
            As[nb][(lkq + 2) * 132 + lm] = av.z;
            As[nb][(lkq + 3) * 132 + lm] = av.w;
            *(float4*)(&Bs[nb][lkr * 128 + lnq]) = bv;
            __syncthreads();
            buf = nb;
        }
    }

#pragma unroll
    for (int i = 0; i < 8; i++) {
        const int m = m0 + ty * 8 + i;
        float* dst = Pout + (size_t)m * 1536 + n0 + tx * 8;
        const float2 v0 = unpack2(acc2[i][0]);
        const float2 v1 = unpack2(acc2[i][1]);
        const float2 v2 = unpack2(acc2[i][2]);
        const float2 v3 = unpack2(acc2[i][3]);
        *(float4*)(dst)     = make_float4(v0.x, v0.y, v1.x, v1.y);
        *(float4*)(dst + 4) = make_float4(v2.x, v2.y, v3.x, v3.y);
    }
}

// ---------------------------------------------------------------------------
// Kernel A2: combine split-K partials + bias, scatter to Q/K/V.
// ---------------------------------------------------------------------------
__global__ void __launch_bounds__(256) qkv_combine_kernel(
    const float* __restrict__ bias)
{
    const int idx = blockIdx.x * 256 + threadIdx.x;     // float4 index
    const float4 a = ((const float4*)g_P0)[idx];
    const float4 b = ((const float4*)g_P1)[idx];
    const int m  = idx / 384;          // 1536/4
    const int n  = (idx - m * 384) * 4;
    const float4 bs = *(const float4*)(bias + n);

    const int bb = m >> 9;
    const int s  = m & 511;
    const int h  = n / 96;
    const int r  = n - h * 96;
    const int t3 = r >> 5;
    const int d  = r & 31;
    float* dst = (t3 == 0) ? g_Q : ((t3 == 1) ? g_K : g_V);
    *(float4*)(dst + ((size_t)(bb * H_ + h) * S_ + s) * DH_ + d) =
        make_float4(a.x + b.x + bs.x, a.y + b.y + bs.y,
                    a.z + b.z + bs.z, a.w + b.w + bs.w);
}

// ---------------------------------------------------------------------------
// Kernel B (REWRITTEN): folded edge projection, 2j x 8h microtile.
// CTA = (b,i), 256 threads = 128 j-pair groups x 2 head-groups.
// j-chunks of 256 (2 per row); e-blocks of 32 staged in swizzled transposed
// tile pT[32e][260] (col = j ^ ((e>>2)<<2) -> conflict-free STS and LDS.64).
// Per e per warp: 2 wf (pT) + 2 wf (Wc bcast) per 512 MACs = 128 MACs/wf.
// LDG prefetch pipelined across e-blocks. Mask folded into output.
// ---------------------------------------------------------------------------
__global__ void __launch_bounds__(256) radd_kernel(
    const float* __restrict__ P, const float* __restrict__ Wrqk,
    const float* __restrict__ brqk, const int* __restrict__ mask)
{
    __shared__ __align__(16) float pT[32 * 260];   // 33.3 KB, swizzled [e][j']
    __shared__ __align__(16) float Wc[128 * 16];   // folded weights [e][h]
    __shared__ float kss[16], qss[16], badd[16];

    const int i  = blockIdx.x;
    const int b  = blockIdx.y;
    const int tid = threadIdx.x;

    // --- inline ksum/qsum: threads 0..127 -> ksum, 128..255 -> qsum ---
    {
        const float* src = (tid < 128) ? g_K : g_Q;
        const int t  = tid & 127;
        const int hh = t >> 3;
        const int d4 = t & 7;
        const float4 vv = *(const float4*)(src + ((size_t)(b * H_ + hh) * S_ + i) * DH_ + d4 * 4);
        float s = (vv.x + vv.y) + (vv.z + vv.w);
        s += __shfl_xor_sync(0xffffffffu, s, 1);
        s += __shfl_xor_sync(0xffffffffu, s, 2);
        s += __shfl_xor_sync(0xffffffffu, s, 4);
        if (d4 == 0) { if (tid < 128) kss[hh] = s; else qss[hh] = s; }
    }
    __syncthreads();

    // folded weights + bias (once per (b,i) row)
#pragma unroll
    for (int u = 0; u < 8; u++) {
        const int f = tid + u * 256;
        const int e = f >> 4;
        const int h = f & 15;
        Wc[f] = Wrqk[e * 32 + 2 * h] * kss[h] + Wrqk[e * 32 + 2 * h + 1] * qss[h];
    }
    if (tid < 16)
        badd[tid] = brqk[2 * tid] * kss[tid] + brqk[2 * tid + 1] * qss[tid];

    const float4* pg4 = (const float4*)(P + ((size_t)(b * S_ + i)) * S_ * E_);
    const int* mrow = mask + ((size_t)(b * S_ + i)) * S_;

    const int jg = tid & 127;     // j-pair group (j = 2jg, 2jg+1 within chunk)
    const int hg = tid >> 7;      // 0/1 -> heads hg*8 .. hg*8+7
    const int j2 = jg * 2;

    // prefetch block (c=0, eb=0): idx -> j_local = idx>>3, e4 = idx&7
    float4 pr[8];
#pragma unroll
    for (int u = 0; u < 8; u++) {
        const int idx = tid + u * 256;
        pr[u] = pg4[(size_t)(idx >> 3) * 32 + (idx & 7)];
    }

    for (int c = 0; c < 2; c++) {
        ull acc2[2][4];
#pragma unroll
        for (int a = 0; a < 2; a++)
#pragma unroll
            for (int q = 0; q < 4; q++) acc2[a][q] = 0ULL;

        for (int eb = 0; eb < 4; eb++) {
            __syncthreads();   // pT free (also orders Wc/kss on first pass)

            // transpose-store prefetched block into swizzled pT
#pragma unroll
            for (int u = 0; u < 8; u++) {
                const int idx = tid + u * 256;
                const int jl  = idx >> 3;        // 0..255
                const int e4  = idx & 7;         // 0..7
                const int col = jl ^ (e4 << 2);  // swizzle
                pT[(e4 * 4 + 0) * 260 + col] = pr[u].x;
                pT[(e4 * 4 + 1) * 260 + col] = pr[u].y;
                pT[(e4 * 4 + 2) * 260 + col] = pr[u].z;
                pT[(e4 * 4 + 3) * 260 + col] = pr[u].w;
            }

            // prefetch next (c,eb) block (in flight during compute)
            const int n = c * 4 + eb + 1;
            if (n < 8) {
                const int cn  = n >> 2;
                const int ebn = n & 3;
#pragma unroll
                for (int u = 0; u < 8; u++) {
                    const int idx = tid + u * 256;
                    pr[u] = pg4[(size_t)(cn * 256 + (idx >> 3)) * 32 + ebn * 8 + (idx & 7)];
                }
            }
            __syncthreads();   // pT ready

            const float* WcE = Wc + (eb * 32) * 16 + hg * 8;
#pragma unroll 8
            for (int e = 0; e < 32; e++) {
                const int col = j2 ^ ((e >> 2) << 2);
                const float2 pp = *(const float2*)(pT + e * 260 + col);
                const ulonglong2 w01 = *(const ulonglong2*)(WcE + e * 16);
                const ulonglong2 w23 = *(const ulonglong2*)(WcE + e * 16 + 4);
                const ull p0 = pack2(pp.x, pp.x);
                const ull p1 = pack2(pp.y, pp.y);
                ffma2(acc2[0][0], p0, w01.x);
                ffma2(acc2[0][1], p0, w01.y);
                ffma2(acc2[0][2], p0, w23.x);
                ffma2(acc2[0][3], p0, w23.y);
                ffma2(acc2[1][0], p1, w01.x);
                ffma2(acc2[1][1], p1, w01.y);
                ffma2(acc2[1][2], p1, w23.x);
                ffma2(acc2[1][3], p1, w23.y);
            }
        }

        // epilogue for this 256-j chunk
        const int jb  = c * 256 + j2;
        const int mv0 = mrow[jb];
        const int mv1 = mrow[jb + 1];
#pragma unroll
        for (int hp = 0; hp < 4; hp++) {
            const int h0 = hg * 8 + hp * 2;
            const int h1 = h0 + 1;
            const float2 v0 = unpack2(acc2[0][hp]);   // j = jb
            const float2 v1 = unpack2(acc2[1][hp]);   // j = jb+1
            const size_t r0 = ((size_t)(b * H_ + h0) * S_ + i) * S_;
            const size_t r1 = ((size_t)(b * H_ + h1) * S_ + i) * S_;
            g_RADD[r0 + jb]     = mv0 ? (v0.x + badd[h0]) * SCALE_L2E : MASKED_SCORE;
            g_RADD[r1 + jb]     = mv0 ? (v0.y + badd[h1]) * SCALE_L2E : MASKED_SCORE;
            g_RADD[r0 + jb + 1] = mv1 ? (v1.x + badd[h0]) * SCALE_L2E : MASKED_SCORE;
            g_RADD[r1 + jb + 1] = mv1 ? (v1.y + badd[h1]) * SCALE_L2E : MASKED_SCORE;
        }
    }
}

// ---------------------------------------------------------------------------
// Kernel C: fused attention (unchanged from R14).
// ---------------------------------------------------------------------------
__global__ void __launch_bounds__(256, 3) attn_kernel(float* __restrict__ out)
{
    __shared__ __align__(16) float q_s[32 * 68];   // [d][i], pre-scaled
    __shared__ __align__(16) float k_s[32 * 68];   // [d][j]
    __shared__ __align__(16) float v_s[32 * 68];   // [d][j]
    __shared__ __align__(16) float s_s[64 * 68];   // [i][j] probs

    const int b  = blockIdx.z;
    const int h  = blockIdx.y;
    const int i0 = blockIdx.x * 64;
    const int tid  = threadIdx.x;
    const int tx = tid & 15;
    const int ty = tid >> 4;

    const size_t bh = (size_t)(b * H_ + h);
    const float* kg_base = g_K + (bh * S_) * DH_;
    const float* vg_base = g_V + (bh * S_) * DH_;

    // load q tile transposed, pre-scaled
    {
        const float* qg = g_Q + (bh * S_ + i0) * DH_;
#pragma unroll
        for (int u = 0; u < 8; u++) {
            const int f = tid + u * 256;
            const int i = f >> 5;
            const int d = f & 31;
            q_s[d * 68 + i] = qg[f] * SCALE_L2E;
        }
    }

    // stage tile 0
    {
        const float4* kg4 = (const float4*)kg_base;
        const float4* vg4 = (const float4*)vg_base;
#pragma unroll
        for (int u = 0; u < 2; u++) {
            const int f4 = tid + u * 256;
            const int j  = f4 >> 3;
            const int d0 = (f4 & 7) * 4;
            const float4 kv = kg4[f4];
            const float4 vv = vg4[f4];
            k_s[(d0 + 0) * 68 + j] = kv.x;
            k_s[(d0 + 1) * 68 + j] = kv.y;
            k_s[(d0 + 2) * 68 + j] = kv.z;
            k_s[(d0 + 3) * 68 + j] = kv.w;
            v_s[(d0 + 0) * 68 + j] = vv.x;
            v_s[(d0 + 1) * 68 + j] = vv.y;
            v_s[(d0 + 2) * 68 + j] = vv.z;
            v_s[(d0 + 3) * 68 + j] = vv.w;
        }
    }
    __syncthreads();

    float m4[4], l4[4];
#pragma unroll
    for (int ii = 0; ii < 4; ii++) { m4[ii] = MASKED_SCORE; l4[ii] = 0.0f; }

    ull accJ[4][2];
#pragma unroll
    for (int a = 0; a < 4; a++) { accJ[a][0] = 0ULL; accJ[a][1] = 0ULL; }

    for (int t = 0; t < 8; t++) {
        const int j0 = t * 64;
        const bool hasn = (t < 7);

        // prefetch next k tile into registers (v loaded at stage time)
        float4 kr[2];
        if (hasn) {
            const float4* kg4 = (const float4*)(kg_base + (size_t)(j0 + 64) * DH_);
#pragma unroll
            for (int u = 0; u < 2; u++)
                kr[u] = kg4[tid + u * 256];
        }

        // prefetch RADD (mask already folded in)
        float4 r4[4];
#pragma unroll
        for (int ii = 0; ii < 4; ii++) {
            const int i = i0 + ty * 4 + ii;
            r4[ii] = *(const float4*)(g_RADD + (bh * S_ + i) * S_ + j0 + tx * 4);
        }

        // --- QK^T 64x64, FFMA2 pairs over j ---
        ull acc2[4][2];
#pragma unroll
        for (int a = 0; a < 4; a++) { acc2[a][0] = 0ULL; acc2[a][1] = 0ULL; }

#pragma unroll
        for (int d = 0; d < 32; d++) {
            float av[4];
            *(float4*)(av) = *(const float4*)(q_s + d * 68 + ty * 4);
            const ulonglong2 bq = *(const ulonglong2*)(k_s + d * 68 + tx * 4);
#pragma unroll
            for (int ii = 0; ii < 4; ii++) {
                const ull ap = pack2(av[ii], av[ii]);
                ffma2(acc2[ii][0], ap, bq.x);
                ffma2(acc2[ii][1], ap, bq.y);
            }
        }

        // --- softmax fully in registers (16-lane j-group reduction) ---
#pragma unroll
        for (int ii = 0; ii < 4; ii++) {
            const float2 p01 = unpack2(acc2[ii][0]);
            const float2 p23 = unpack2(acc2[ii][1]);
            const float x0 = p01.x + r4[ii].x;
            const float x1 = p01.y + r4[ii].y;
            const float x2 = p23.x + r4[ii].z;
            const float x3 = p23.y + r4[ii].w;

            float mx = fmaxf(fmaxf(x0, x1), fmaxf(x2, x3));
#pragma unroll
            for (int off = 8; off > 0; off >>= 1)
                mx = fmaxf(mx, __shfl_xor_sync(0xffffffffu, mx, off));

            const float m_new = fmaxf(m4[ii], mx);
            const float e0 = exp2f(x0 - m_new);
            const float e1 = exp2f(x1 - m_new);
            const float e2 = exp2f(x2 - m_new);
            const float e3 = exp2f(x3 - m_new);

            float sm = (e0 + e1) + (e2 + e3);
#pragma unroll
            for (int off = 8; off > 0; off >>= 1)
                sm += __shfl_xor_sync(0xffffffffu, sm, off);

            const float alpha = exp2f(m4[ii] - m_new);
            l4[ii] = l4[ii] * alpha + sm;
            m4[ii] = m_new;

            const ull ap = pack2(alpha, alpha);
            accJ[ii][0] = fmul2(accJ[ii][0], ap);
            accJ[ii][1] = fmul2(accJ[ii][1], ap);

            *(float4*)(s_s + (ty * 4 + ii) * 68 + tx * 4) = make_float4(e0, e1, e2, e3);
        }
        __syncthreads();   // probs visible

        // --- PV: thread = 4i x 2d, FFMA2 packed over (even j, odd j) ---
        const int ib = ty * 4;
        const int d0 = tx * 2;
#pragma unroll 4
        for (int j4 = 0; j4 < 64; j4 += 4) {
            const ulonglong2 v0 = *(const ulonglong2*)(v_s + (d0 + 0) * 68 + j4);
            const ulonglong2 v1 = *(const ulonglong2*)(v_s + (d0 + 1) * 68 + j4);
#pragma unroll
            for (int ii = 0; ii < 4; ii++) {
                const ulonglong2 pp = *(const ulonglong2*)(s_s + (ib + ii) * 68 + j4);
                ffma2(accJ[ii][0], pp.x, v0.x);
                ffma2(accJ[ii][0], pp.y, v0.y);
                ffma2(accJ[ii][1], pp.x, v1.x);
                ffma2(accJ[ii][1], pp.y, v1.y);
            }
        }

        if (hasn) {
            __syncthreads();   // all reads of k_s/v_s/s_s done
            const float4* vg4 = (const float4*)(vg_base + (size_t)(j0 + 64) * DH_);
#pragma unroll
            for (int u = 0; u < 2; u++) {
                const int f4 = tid + u * 256;
                const int j  = f4 >> 3;
                const int dd = (f4 & 7) * 4;
                const float4 vv = vg4[f4];
                k_s[(dd + 0) * 68 + j] = kr[u].x;
                k_s[(dd + 1) * 68 + j] = kr[u].y;
                k_s[(dd + 2) * 68 + j] = kr[u].z;
                k_s[(dd + 3) * 68 + j] = kr[u].w;
                v_s[(dd + 0) * 68 + j] = vv.x;
                v_s[(dd + 1) * 68 + j] = vv.y;
                v_s[(dd + 2) * 68 + j] = vv.z;
                v_s[(dd + 3) * 68 + j] = vv.w;
            }
            __syncthreads();   // new tile visible
        }
    }

    // epilogue
    const int ib = ty * 4;
    const int d0 = tx * 2;
#pragma unroll
    for (int ii = 0; ii < 4; ii++) {
        const float inv = 1.0f / l4[ii];
        const float2 o0 = unpack2(accJ[ii][0]);
        const float2 o1 = unpack2(accJ[ii][1]);
        float2 res;
        res.x = (o0.x + o0.y) * inv;
        res.y = (o1.x + o1.y) * inv;
        *(float2*)(out + ((size_t)(b * S_ + i0 + ib + ii)) * D_ + h * DH_ + d0) = res;
    }
}

// ---------------------------------------------------------------------------
extern "C" void kernel_launch(void* const* d_in, const int* in_sizes, int n_in,
                              void* d_out, int out_size)
{
    const float* x     = (const float*)d_in[0];
    const float* p     = (const float*)d_in[1];
    const int*   mask  = (const int*)  d_in[2];
    const float* Wqkv  = (const float*)d_in[3];
    const float* bqkv  = (const float*)d_in[4];
    const float* Wrqk  = (const float*)d_in[5];
    const float* brqk  = (const float*)d_in[6];
    float* out = (float*)d_out;

    (void)in_sizes; (void)n_in; (void)out_size;

    qkv_gemm_kernel<<<dim3(1536 / 128, 2048 / 128, 2), 256>>>(x, Wqkv);
    qkv_combine_kernel<<<(2048 * 1536 / 4) / 256, 256>>>(bqkv);
    radd_kernel<<<dim3(S_, B_), 256>>>(p, Wrqk, brqk, mask);
    attn_kernel<<<dim3(S_ / 64, H_, B_), 256>>>(out);
}

// round 17
// speedup vs baseline: 1.0989x; 1.0989x over previous
#include <cuda_runtime.h>
#include <cuda_bf16.h>

#define B_  4
#define S_  512
#define D_  512
#define H_  16
#define DH_ 32
#define E_  128

typedef unsigned long long ull;

// ---- f32x2 packed-math helpers (sm_103a FFMA2 path, PTX-only) -------------
__device__ __forceinline__ ull pack2(float x, float y) {
    ull r; asm("mov.b64 %0, {%1, %2};" : "=l"(r) : "f"(x), "f"(y)); return r;
}
__device__ __forceinline__ void ffma2(ull& d, ull a, ull b) {
    asm("fma.rn.f32x2 %0, %1, %2, %0;" : "+l"(d) : "l"(a), "l"(b));
}
__device__ __forceinline__ ull fmul2(ull a, ull b) {
    ull r; asm("mul.rn.f32x2 %0, %1, %2;" : "=l"(r) : "l"(a), "l"(b)); return r;
}
__device__ __forceinline__ float2 unpack2(ull v) {
    float2 f; asm("mov.b64 {%0, %1}, %2;" : "=f"(f.x), "=f"(f.y) : "l"(v)); return f;
}

// scale * log2(e): scores pre-multiplied so softmax uses exp2f directly.
#define SCALE_L2E (0.10206207261596576f * 1.4426950408889634f)
#define MASKED_SCORE (-1e30f)

// fp32 scratch (static device globals; no allocation anywhere)
__device__ float g_Q[B_*H_*S_*DH_];
__device__ float g_K[B_*H_*S_*DH_];
__device__ float g_V[B_*H_*S_*DH_];
__device__ float g_P0[2048 * 1536];     // split-K partial 0
__device__ float g_P1[2048 * 1536];     // split-K partial 1
__device__ float g_RADD[B_*H_*S_*S_];   // folded edge term * SCALE_L2E, mask folded in

// ---------------------------------------------------------------------------
// Kernel A: split-K qkv GEMM (unchanged).
// ---------------------------------------------------------------------------
__global__ void __launch_bounds__(256) qkv_gemm_kernel(
    const float* __restrict__ X, const float* __restrict__ W)
{
    __shared__ __align__(16) float As[2][8 * 132];
    __shared__ __align__(16) float Bs[2][8 * 128];

    const int m0 = blockIdx.y * 128;
    const int n0 = blockIdx.x * 128;
    const int ks = blockIdx.z * 256;
    float* __restrict__ Pout = blockIdx.z ? g_P1 : g_P0;

    const int tid = threadIdx.x;
    const int tx = tid & 15;
    const int ty = tid >> 4;

    const int lm  = tid >> 1;
    const int lkq = (tid & 1) * 4;
    const int lkr = tid >> 5;
    const int lnq = (tid & 31) * 4;

    const float* Ag = X + (size_t)(m0 + lm) * 512 + ks + lkq;
    const float* Bg = W + (size_t)(ks + lkr) * 1536 + n0 + lnq;

    ull acc2[8][4];
#pragma unroll
    for (int i = 0; i < 8; i++)
#pragma unroll
        for (int j = 0; j < 4; j++) acc2[i][j] = 0ULL;

    {
        float4 av = *(const float4*)(Ag);
        float4 bv = *(const float4*)(Bg);
        As[0][(lkq + 0) * 132 + lm] = av.x;
        As[0][(lkq + 1) * 132 + lm] = av.y;
        As[0][(lkq + 2) * 132 + lm] = av.z;
        As[0][(lkq + 3) * 132 + lm] = av.w;
        *(float4*)(&Bs[0][lkr * 128 + lnq]) = bv;
    }
    __syncthreads();

    int buf = 0;
    for (int k0 = 0; k0 < 256; k0 += 8) {
        const bool has_next = (k0 + 8) < 256;
        float4 av, bv;
        if (has_next) {
            av = *(const float4*)(Ag + k0 + 8);
            bv = *(const float4*)(Bg + (size_t)(k0 + 8) * 1536);
        }

        const float* Asb = As[buf];
        const float* Bsb = Bs[buf];
#pragma unroll
        for (int kk = 0; kk < 8; kk++) {
            float a[8];
            *(float4*)(a)     = *(const float4*)(Asb + kk * 132 + ty * 8);
            *(float4*)(a + 4) = *(const float4*)(Asb + kk * 132 + ty * 8 + 4);
            ulonglong2 b01 = *(const ulonglong2*)(Bsb + kk * 128 + tx * 8);
            ulonglong2 b23 = *(const ulonglong2*)(Bsb + kk * 128 + tx * 8 + 4);
            ull bp0 = b01.x, bp1 = b01.y, bp2 = b23.x, bp3 = b23.y;
#pragma unroll
            for (int i = 0; i < 8; i++) {
                const ull ap = pack2(a[i], a[i]);
                ffma2(acc2[i][0], ap, bp0);
                ffma2(acc2[i][1], ap, bp1);
                ffma2(acc2[i][2], ap, bp2);
                ffma2(acc2[i][3], ap, bp3);
            }
        }

        if (has_next) {
            const int nb = buf ^ 1;
            As[nb][(lkq + 0) * 132 + lm] = av.x;
            As[nb][(lkq + 1) * 132 + lm] = av.y;
            As[nb][(lkq + 2) * 132 + lm] = av.z;
            As[nb][(lkq + 3) * 132 + lm] = av.w;
            *(float4*)(&Bs[nb][lkr * 128 + lnq]) = bv;
            __syncthreads();
            buf = nb;
        }
    }

#pragma unroll
    for (int i = 0; i < 8; i++) {
        const int m = m0 + ty * 8 + i;
        float* dst = Pout + (size_t)m * 1536 + n0 + tx * 8;
        const float2 v0 = unpack2(acc2[i][0]);
        const float2 v1 = unpack2(acc2[i][1]);
        const float2 v2 = unpack2(acc2[i][2]);
        const float2 v3 = unpack2(acc2[i][3]);
        *(float4*)(dst)     = make_float4(v0.x, v0.y, v1.x, v1.y);
        *(float4*)(dst + 4) = make_float4(v2.x, v2.y, v3.x, v3.y);
    }
}

// ---------------------------------------------------------------------------
// Kernel A2: combine split-K partials + bias, scatter to Q/K/V (unchanged).
// ---------------------------------------------------------------------------
__global__ void __launch_bounds__(256) qkv_combine_kernel(
    const float* __restrict__ bias)
{
    const int idx = blockIdx.x * 256 + threadIdx.x;     // float4 index
    const float4 a = ((const float4*)g_P0)[idx];
    const float4 b = ((const float4*)g_P1)[idx];
    const int m  = idx / 384;          // 1536/4
    const int n  = (idx - m * 384) * 4;
    const float4 bs = *(const float4*)(bias + n);

    const int bb = m >> 9;
    const int s  = m & 511;
    const int h  = n / 96;
    const int r  = n - h * 96;
    const int t3 = r >> 5;
    const int d  = r & 31;
    float* dst = (t3 == 0) ? g_Q : ((t3 == 1) ? g_K : g_V);
    *(float4*)(dst + ((size_t)(bb * H_ + h) * S_ + s) * DH_ + d) =
        make_float4(a.x + b.x + bs.x, a.y + b.y + bs.y,
                    a.z + b.z + bs.z, a.w + b.w + bs.w);
}

// ---------------------------------------------------------------------------
// Kernel B: folded edge projection, 2j x 8h microtile (unchanged from R15).
// ---------------------------------------------------------------------------
__global__ void __launch_bounds__(256) radd_kernel(
    const float* __restrict__ P, const float* __restrict__ Wrqk,
    const float* __restrict__ brqk, const int* __restrict__ mask)
{
    __shared__ __align__(16) float pT[32 * 260];   // swizzled [e][j']
    __shared__ __align__(16) float Wc[128 * 16];   // folded weights [e][h]
    __shared__ float kss[16], qss[16], badd[16];

    const int i  = blockIdx.x;
    const int b  = blockIdx.y;
    const int tid = threadIdx.x;

    {
        const float* src = (tid < 128) ? g_K : g_Q;
        const int t  = tid & 127;
        const int hh = t >> 3;
        const int d4 = t & 7;
        const float4 vv = *(const float4*)(src + ((size_t)(b * H_ + hh) * S_ + i) * DH_ + d4 * 4);
        float s = (vv.x + vv.y) + (vv.z + vv.w);
        s += __shfl_xor_sync(0xffffffffu, s, 1);
        s += __shfl_xor_sync(0xffffffffu, s, 2);
        s += __shfl_xor_sync(0xffffffffu, s, 4);
        if (d4 == 0) { if (tid < 128) kss[hh] = s; else qss[hh] = s; }
    }
    __syncthreads();

#pragma unroll
    for (int u = 0; u < 8; u++) {
        const int f = tid + u * 256;
        const int e = f >> 4;
        const int h = f & 15;
        Wc[f] = Wrqk[e * 32 + 2 * h] * kss[h] + Wrqk[e * 32 + 2 * h + 1] * qss[h];
    }
    if (tid < 16)
        badd[tid] = brqk[2 * tid] * kss[tid] + brqk[2 * tid + 1] * qss[tid];

    const float4* pg4 = (const float4*)(P + ((size_t)(b * S_ + i)) * S_ * E_);
    const int* mrow = mask + ((size_t)(b * S_ + i)) * S_;

    const int jg = tid & 127;
    const int hg = tid >> 7;
    const int j2 = jg * 2;

    float4 pr[8];
#pragma unroll
    for (int u = 0; u < 8; u++) {
        const int idx = tid + u * 256;
        pr[u] = pg4[(size_t)(idx >> 3) * 32 + (idx & 7)];
    }

    for (int c = 0; c < 2; c++) {
        ull acc2[2][4];
#pragma unroll
        for (int a = 0; a < 2; a++)
#pragma unroll
            for (int q = 0; q < 4; q++) acc2[a][q] = 0ULL;

        for (int eb = 0; eb < 4; eb++) {
            __syncthreads();

#pragma unroll
            for (int u = 0; u < 8; u++) {
                const int idx = tid + u * 256;
                const int jl  = idx >> 3;
                const int e4  = idx & 7;
                const int col = jl ^ (e4 << 2);
                pT[(e4 * 4 + 0) * 260 + col] = pr[u].x;
                pT[(e4 * 4 + 1) * 260 + col] = pr[u].y;
                pT[(e4 * 4 + 2) * 260 + col] = pr[u].z;
                pT[(e4 * 4 + 3) * 260 + col] = pr[u].w;
            }

            const int n = c * 4 + eb + 1;
            if (n < 8) {
                const int cn  = n >> 2;
                const int ebn = n & 3;
#pragma unroll
                for (int u = 0; u < 8; u++) {
                    const int idx = tid + u * 256;
                    pr[u] = pg4[(size_t)(cn * 256 + (idx >> 3)) * 32 + ebn * 8 + (idx & 7)];
                }
            }
            __syncthreads();

            const float* WcE = Wc + (eb * 32) * 16 + hg * 8;
#pragma unroll 8
            for (int e = 0; e < 32; e++) {
                const int col = j2 ^ ((e >> 2) << 2);
                const float2 pp = *(const float2*)(pT + e * 260 + col);
                const ulonglong2 w01 = *(const ulonglong2*)(WcE + e * 16);
                const ulonglong2 w23 = *(const ulonglong2*)(WcE + e * 16 + 4);
                const ull p0 = pack2(pp.x, pp.x);
                const ull p1 = pack2(pp.y, pp.y);
                ffma2(acc2[0][0], p0, w01.x);
                ffma2(acc2[0][1], p0, w01.y);
                ffma2(acc2[0][2], p0, w23.x);
                ffma2(acc2[0][3], p0, w23.y);
                ffma2(acc2[1][0], p1, w01.x);
                ffma2(acc2[1][1], p1, w01.y);
                ffma2(acc2[1][2], p1, w23.x);
                ffma2(acc2[1][3], p1, w23.y);
            }
        }

        const int jb  = c * 256 + j2;
        const int mv0 = mrow[jb];
        const int mv1 = mrow[jb + 1];
#pragma unroll
        for (int hp = 0; hp < 4; hp++) {
            const int h0 = hg * 8 + hp * 2;
            const int h1 = h0 + 1;
            const float2 v0 = unpack2(acc2[0][hp]);
            const float2 v1 = unpack2(acc2[1][hp]);
            const size_t r0 = ((size_t)(b * H_ + h0) * S_ + i) * S_;
            const size_t r1 = ((size_t)(b * H_ + h1) * S_ + i) * S_;
            g_RADD[r0 + jb]     = mv0 ? (v0.x + badd[h0]) * SCALE_L2E : MASKED_SCORE;
            g_RADD[r1 + jb]     = mv0 ? (v0.y + badd[h1]) * SCALE_L2E : MASKED_SCORE;
            g_RADD[r0 + jb + 1] = mv1 ? (v1.x + badd[h0]) * SCALE_L2E : MASKED_SCORE;
            g_RADD[r1 + jb + 1] = mv1 ? (v1.y + badd[h1]) * SCALE_L2E : MASKED_SCORE;
        }
    }
}

// ---------------------------------------------------------------------------
// Kernel C (REWRITTEN): fused attention, 128 threads/CTA.
// QK: thread = 4i x 8j (j split in halves tx*4 and 32+tx*4 -> bank-perfect);
//     RADD loaded directly into the accumulators (scores = RADD + QK).
// PV: thread = 4i x 4d with d strided by 8 (bank = 4tx+j4 -> conflict-free).
// Softmax in registers, 3-round 8-lane shuffles. 43.5 KB smem, 4+ CTAs/SM.
// ---------------------------------------------------------------------------
__global__ void __launch_bounds__(128, 4) attn_kernel(float* __restrict__ out)
{
    __shared__ __align__(16) float q_s[32 * 68];   // [d][i], pre-scaled
    __shared__ __align__(16) float k_s[32 * 68];   // [d][j]
    __shared__ __align__(16) float v_s[32 * 68];   // [d][j]
    __shared__ __align__(16) float s_s[64 * 68];   // [i][j] probs

    const int b  = blockIdx.z;
    const int h  = blockIdx.y;
    const int i0 = blockIdx.x * 64;
    const int tid = threadIdx.x;
    const int tx = tid & 7;         // QK: j-octant | PV: d residue
    const int ty = tid >> 3;        // i-group: rows ty*4 .. ty*4+3

    const size_t bh = (size_t)(b * H_ + h);
    const float* kg_base = g_K + (bh * S_) * DH_;
    const float* vg_base = g_V + (bh * S_) * DH_;

    // load q tile transposed, pre-scaled (512 float4, 4 per thread)
    {
        const float4* qg4 = (const float4*)(g_Q + (bh * S_ + i0) * DH_);
#pragma unroll
        for (int u = 0; u < 4; u++) {
            const int f4 = tid + u * 128;
            const int i  = f4 >> 3;
            const int d0 = (f4 & 7) * 4;
            const float4 qv = qg4[f4];
            q_s[(d0 + 0) * 68 + i] = qv.x * SCALE_L2E;
            q_s[(d0 + 1) * 68 + i] = qv.y * SCALE_L2E;
            q_s[(d0 + 2) * 68 + i] = qv.z * SCALE_L2E;
            q_s[(d0 + 3) * 68 + i] = qv.w * SCALE_L2E;
        }
    }

    // stage tile 0 (k,v transposed)
    {
        const float4* kg4 = (const float4*)kg_base;
        const float4* vg4 = (const float4*)vg_base;
#pragma unroll
        for (int u = 0; u < 4; u++) {
            const int f4 = tid + u * 128;
            const int j  = f4 >> 3;
            const int d0 = (f4 & 7) * 4;
            const float4 kv = kg4[f4];
            const float4 vv = vg4[f4];
            k_s[(d0 + 0) * 68 + j] = kv.x;
            k_s[(d0 + 1) * 68 + j] = kv.y;
            k_s[(d0 + 2) * 68 + j] = kv.z;
            k_s[(d0 + 3) * 68 + j] = kv.w;
            v_s[(d0 + 0) * 68 + j] = vv.x;
            v_s[(d0 + 1) * 68 + j] = vv.y;
            v_s[(d0 + 2) * 68 + j] = vv.z;
            v_s[(d0 + 3) * 68 + j] = vv.w;
        }
    }
    __syncthreads();

    float m4[4], l4[4];
#pragma unroll
    for (int ii = 0; ii < 4; ii++) { m4[ii] = MASKED_SCORE; l4[ii] = 0.0f; }

    ull accJ[4][4];                 // [i-sub][d-sub], packed over (even j, odd j)
#pragma unroll
    for (int a = 0; a < 4; a++)
#pragma unroll
        for (int s = 0; s < 4; s++) accJ[a][s] = 0ULL;

    for (int t = 0; t < 8; t++) {
        const int j0 = t * 64;
        const bool hasn = (t < 7);

        // scores accumulators initialized from RADD (mask pre-folded)
        ull acc2[4][4];   // [i-sub][{A01,A23,B01,B23}]
#pragma unroll
        for (int ii = 0; ii < 4; ii++) {
            const float* rb = g_RADD + (bh * S_ + i0 + ty * 4 + ii) * S_ + j0;
            const float4 ra = *(const float4*)(rb + tx * 4);
            const float4 rbq = *(const float4*)(rb + 32 + tx * 4);
            acc2[ii][0] = pack2(ra.x, ra.y);
            acc2[ii][1] = pack2(ra.z, ra.w);
            acc2[ii][2] = pack2(rbq.x, rbq.y);
            acc2[ii][3] = pack2(rbq.z, rbq.w);
        }

        // --- QK^T: 4i x 8j per thread, j in two bank-perfect halves ---
#pragma unroll
        for (int d = 0; d < 32; d++) {
            float av[4];
            *(float4*)(av) = *(const float4*)(q_s + d * 68 + ty * 4);
            const ulonglong2 kA = *(const ulonglong2*)(k_s + d * 68 + tx * 4);
            const ulonglong2 kB = *(const ulonglong2*)(k_s + d * 68 + 32 + tx * 4);
#pragma unroll
            for (int ii = 0; ii < 4; ii++) {
                const ull ap = pack2(av[ii], av[ii]);
                ffma2(acc2[ii][0], ap, kA.x);
                ffma2(acc2[ii][1], ap, kA.y);
                ffma2(acc2[ii][2], ap, kB.x);
                ffma2(acc2[ii][3], ap, kB.y);
            }
        }

        // --- softmax in registers (8-lane j-group reduction, 3 rounds) ---
#pragma unroll
        for (int ii = 0; ii < 4; ii++) {
            const float2 a01 = unpack2(acc2[ii][0]);
            const float2 a23 = unpack2(acc2[ii][1]);
            const float2 b01 = unpack2(acc2[ii][2]);
            const float2 b23 = unpack2(acc2[ii][3]);

            float mx = fmaxf(fmaxf(fmaxf(a01.x, a01.y), fmaxf(a23.x, a23.y)),
                             fmaxf(fmaxf(b01.x, b01.y), fmaxf(b23.x, b23.y)));
#pragma unroll
            for (int off = 4; off > 0; off >>= 1)
                mx = fmaxf(mx, __shfl_xor_sync(0xffffffffu, mx, off));

            const float m_new = fmaxf(m4[ii], mx);
            const float e0 = exp2f(a01.x - m_new);
            const float e1 = exp2f(a01.y - m_new);
            const float e2 = exp2f(a23.x - m_new);
            const float e3 = exp2f(a23.y - m_new);
            const float e4 = exp2f(b01.x - m_new);
            const float e5 = exp2f(b01.y - m_new);
            const float e6 = exp2f(b23.x - m_new);
            const float e7 = exp2f(b23.y - m_new);

            float sm = ((e0 + e1) + (e2 + e3)) + ((e4 + e5) + (e6 + e7));
#pragma unroll
            for (int off = 4; off > 0; off >>= 1)
                sm += __shfl_xor_sync(0xffffffffu, sm, off);

            const float alpha = exp2f(m4[ii] - m_new);
            l4[ii] = l4[ii] * alpha + sm;
            m4[ii] = m_new;

            const ull ap = pack2(alpha, alpha);
            accJ[ii][0] = fmul2(accJ[ii][0], ap);
            accJ[ii][1] = fmul2(accJ[ii][1], ap);
            accJ[ii][2] = fmul2(accJ[ii][2], ap);
            accJ[ii][3] = fmul2(accJ[ii][3], ap);

            const int row = ty * 4 + ii;
            *(float4*)(s_s + row * 68 + tx * 4)      = make_float4(e0, e1, e2, e3);
            *(float4*)(s_s + row * 68 + 32 + tx * 4) = make_float4(e4, e5, e6, e7);
        }
        __syncthreads();   // probs visible

        // --- PV: 4i x 4d per thread, d = tx + 8s (bank-perfect v reads) ---
#pragma unroll 4
        for (int j4 = 0; j4 < 64; j4 += 4) {
            ulonglong2 vr[4];
#pragma unroll
            for (int s = 0; s < 4; s++)
                vr[s] = *(const ulonglong2*)(v_s + (tx + 8 * s) * 68 + j4);
#pragma unroll
            for (int ii = 0; ii < 4; ii++) {
                const ulonglong2 pp = *(const ulonglong2*)(s_s + (ty * 4 + ii) * 68 + j4);
#pragma unroll
                for (int s = 0; s < 4; s++) {
                    ffma2(accJ[ii][s], pp.x, vr[s].x);
                    ffma2(accJ[ii][s], pp.y, vr[s].y);
                }
            }
        }

        if (hasn) {
            __syncthreads();   // all reads of k_s/v_s/s_s done
            const float4* kg4 = (const float4*)(kg_base + (size_t)(j0 + 64) * DH_);
            const float4* vg4 = (const float4*)(vg_base + (size_t)(j0 + 64) * DH_);
#pragma unroll
            for (int u = 0; u < 4; u++) {
                const int f4 = tid + u * 128;
                const int j  = f4 >> 3;
                const int d0 = (f4 & 7) * 4;
                const float4 kv = kg4[f4];
                const float4 vv = vg4[f4];
                k_s[(d0 + 0) * 68 + j] = kv.x;
                k_s[(d0 + 1) * 68 + j] = kv.y;
                k_s[(d0 + 2) * 68 + j] = kv.z;
                k_s[(d0 + 3) * 68 + j] = kv.w;
                v_s[(d0 + 0) * 68 + j] = vv.x;
                v_s[(d0 + 1) * 68 + j] = vv.y;
                v_s[(d0 + 2) * 68 + j] = vv.z;
                v_s[(d0 + 3) * 68 + j] = vv.w;
            }
            __syncthreads();   // new tile visible
        }
    }

    // epilogue: d = tx + 8s
#pragma unroll
    for (int ii = 0; ii < 4; ii++) {
        const float inv = 1.0f / l4[ii];
        float* orow = out + ((size_t)(b * S_ + i0 + ty * 4 + ii)) * D_ + h * DH_;
#pragma unroll
        for (int s = 0; s < 4; s++) {
            const float2 o = unpack2(accJ[ii][s]);
            orow[tx + 8 * s] = (o.x + o.y) * inv;
        }
    }
}

// ---------------------------------------------------------------------------
extern "C" void kernel_launch(void* const* d_in, const int* in_sizes, int n_in,
                              void* d_out, int out_size)
{
    const float* x     = (const float*)d_in[0];
    const float* p     = (const float*)d_in[1];
    const int*   mask  = (const int*)  d_in[2];
    const float* Wqkv  = (const float*)d_in[3];
    const float* bqkv  = (const float*)d_in[4];
    const float* Wrqk  = (const float*)d_in[5];
    const float* brqk  = (const float*)d_in[6];
    float* out = (float*)d_out;

    (void)in_sizes; (void)n_in; (void)out_size;

    qkv_gemm_kernel<<<dim3(1536 / 128, 2048 / 128, 2), 256>>>(x, Wqkv);
    qkv_combine_kernel<<<(2048 * 1536 / 4) / 256, 256>>>(bqkv);
    radd_kernel<<<dim3(S_, B_), 256>>>(p, Wrqk, brqk, mask);
    attn_kernel<<<dim3(S_ / 64, H_, B_), 128>>>(out);
}